// round 4
// baseline (speedup 1.0000x reference)
#include <cuda_runtime.h>
#include <cuda_bf16.h>

#define B_    64
#define L_    16384
#define D_    64
#define KSEL  256
#define TILE  128
#define NT    4                      // tiles per CTA (double-buffered)
#define ROWW  68
#define NBINS 4096
#define CAP   2048

__device__ float g_sim[B_ * L_];
__device__ unsigned g_hist[B_ * NBINS];   // zero-init; kernel B re-zeroes

__device__ __forceinline__ unsigned f2u(float f) {
    unsigned b = __float_as_uint(f);
    return (b & 0x80000000u) ? ~b : (b | 0x80000000u);
}
__device__ __forceinline__ float u2f(unsigned u) {
    unsigned b = (u & 0x80000000u) ? (u & 0x7FFFFFFFu) : ~u;
    return __uint_as_float(b);
}

// ---------------------------------------------------------------------------
// Kernel A: sims + per-batch 12-bit histogram. 4 tiles/CTA, 2-stage pipeline.
// ---------------------------------------------------------------------------
__global__ void __launch_bounds__(TILE) sim_kernel(
    const float* __restrict__ q,
    const float* __restrict__ keys,
    const float* __restrict__ gp)
{
    extern __shared__ __align__(16) float tile[];   // [2][TILE*ROWW]
    __shared__ __align__(16) float4 qsm[D_ / 4];

    const int b   = blockIdx.y;
    const int t0  = blockIdx.x * (TILE * NT);       // first key of this CTA
    const int tid = threadIdx.x;

    if (tid < D_ / 4)
        qsm[tid] = reinterpret_cast<const float4*>(q + b * D_)[tid];

    const float4* kbase = reinterpret_cast<const float4*>(
        keys + (size_t)b * L_ * D_ + (size_t)t0 * D_);

    // issue tile tt into buffer buf
    auto issue = [&](int tt, int buf) {
        const float4* src = kbase + tt * (TILE * 16);
        float* dstbase = tile + buf * (TILE * ROWW);
#pragma unroll
        for (int j = 0; j < 16; j++) {
            int f = j * TILE + tid;
            int l = f >> 4;
            int c = f & 15;
            unsigned dst = (unsigned)__cvta_generic_to_shared(
                &dstbase[l * ROWW + c * 4]);
            asm volatile("cp.async.cg.shared.global [%0], [%1], 16;\n"
                         :: "r"(dst), "l"(src + f));
        }
        asm volatile("cp.async.commit_group;\n");
    };

    issue(0, 0);

    __syncthreads();   // qsm visible
    float qq = 0.f;
#pragma unroll
    for (int i = 0; i < D_ / 4; i++) {
        float4 t = qsm[i];
        qq += t.x * t.x + t.y * t.y + t.z * t.z + t.w * t.w;
    }
    const float rq = gp[0] * rsqrtf(qq);

#pragma unroll
    for (int t = 0; t < NT; t++) {
        if (t + 1 < NT) {
            issue(t + 1, (t + 1) & 1);
            asm volatile("cp.async.wait_group 1;\n");
        } else {
            asm volatile("cp.async.wait_group 0;\n");
        }
        __syncthreads();   // buffer (t&1) visible to all

        const float* tb = tile + (t & 1) * (TILE * ROWW);
        float dot = 0.f, kk = 0.f;
#pragma unroll
        for (int i = 0; i < 16; i++) {
            float4 kv = *reinterpret_cast<const float4*>(&tb[tid * ROWW + i * 4]);
            float4 qv = qsm[i];
            dot += qv.x * kv.x + qv.y * kv.y + qv.z * kv.z + qv.w * kv.w;
            kk  += kv.x * kv.x + kv.y * kv.y + kv.z * kv.z + kv.w * kv.w;
        }
        float sim = dot * rq * rsqrtf(kk);
        g_sim[b * L_ + t0 + t * TILE + tid] = sim;
        atomicAdd(&g_hist[b * NBINS + (f2u(sim) >> 20)], 1u);

        __syncthreads();   // all done reading buffer before t+2 overwrites it
    }
}

// ---------------------------------------------------------------------------
__device__ __forceinline__ int suffix_select(unsigned part, unsigned need,
                                             unsigned& above_out, int lane) {
    unsigned suf = part;
#pragma unroll
    for (int o = 1; o < 32; o <<= 1) {
        unsigned t = __shfl_down_sync(0xFFFFFFFFu, suf, o);
        if (lane + o < 32) suf += t;
    }
    unsigned above = suf - part;
    unsigned m = __ballot_sync(0xFFFFFFFFu,
                               (above < need) && (above + part >= need));
    int sel = __ffs(m) - 1;
    above_out = __shfl_sync(0xFFFFFFFFu, above, sel);
    return sel;
}

// ---------------------------------------------------------------------------
// Kernel B: per-batch threshold + collect + O(n^2) rank + softmax + gather.
// One CTA per batch, 256 threads, one barrier-heavy phase avoided entirely.
// ---------------------------------------------------------------------------
__global__ void __launch_bounds__(256) topk_kernel(
    const float* __restrict__ values,
    float* __restrict__ out)
{
    __shared__ unsigned hist[NBINS];                       // 16 KB
    __shared__ __align__(16) unsigned long long cand[CAP]; // 16 KB
    __shared__ unsigned long long s_key[KSEL];             // 2 KB
    __shared__ float s_e[KSEL];
    __shared__ float s_sum;
    __shared__ int   s_n;
    __shared__ unsigned s_lo;

    const int b   = blockIdx.x;
    const int tid = threadIdx.x;
    const int T   = 256;

    // 1. histogram -> smem; restore zeros for next graph replay
    for (int i = tid; i < NBINS; i += T) {
        hist[i] = g_hist[b * NBINS + i];
        g_hist[b * NBINS + i] = 0;
    }
    if (tid == 0) s_n = 0;
    __syncthreads();

    // 2. threshold bin (warp 0)
    if (tid < 32) {
        const int lane = tid;
        unsigned part = 0;
        {
            int base = lane * 128;
            for (int j = 0; j < 128; j++) part += hist[base + j];
        }
        unsigned above1;
        int g1 = suffix_select(part, KSEL, above1, lane);
        int base2 = g1 * 128 + lane * 4;
        unsigned part2 = hist[base2] + hist[base2 + 1] +
                         hist[base2 + 2] + hist[base2 + 3];
        unsigned above2;
        int g2 = suffix_select(part2, KSEL - above1, above2, lane);
        int bin_base = g1 * 128 + g2 * 4;
        unsigned acc = above1 + above2;
        int bin = bin_base;
        for (int j = 3; j >= 0; j--) {
            unsigned h = hist[bin_base + j];
            if (acc + h >= KSEL) { bin = bin_base + j; break; }
            acc += h;
        }
        if (lane == 0) s_lo = ((unsigned)bin) << 20;
    }
    __syncthreads();

    // 3. collect candidates >= threshold (warp-aggregated smem atomic)
    const unsigned lo = s_lo;
    const float* simrow = g_sim + b * L_;
#pragma unroll 4
    for (int i = tid; i < L_; i += T) {
        unsigned u = f2u(__ldg(simrow + i));
        bool take = (u >= lo);
        unsigned m = __ballot_sync(0xFFFFFFFFu, take);
        if (m) {
            int lane = tid & 31;
            int leader = __ffs(m) - 1;
            int basepos = 0;
            if (lane == leader)
                basepos = atomicAdd(&s_n, __popc(m));
            basepos = __shfl_sync(0xFFFFFFFFu, basepos, leader);
            if (take) {
                int p = basepos + __popc(m & ((1u << lane) - 1));
                if (p < CAP)
                    cand[p] = ((unsigned long long)u << 32) | (unsigned)(~i);
            }
        }
    }
    __syncthreads();

    // 4. exact rank by pairwise comparison (desc value, asc index on ties)
    int n = s_n; if (n > CAP) n = CAP;
    for (int i = tid; i < n; i += T) {
        unsigned long long me = cand[i];
        int r = 0;
        for (int j = 0; j < n; j++)
            r += (cand[j] > me);
        if (r < KSEL)
            s_key[r] = me;
    }
    __syncthreads();

    // 5. softmax over top-256 (s_key[0] is max) + gather + output
    float maxs = u2f((unsigned)(s_key[0] >> 32));
    float e = 0.f;
    if (tid < KSEL) {
        float s = u2f((unsigned)(s_key[tid] >> 32));
        e = expf(s - maxs);
        s_e[tid] = e;
    }
    __syncthreads();
    if (tid < 32) {
        float acc = 0.f;
        for (int j = tid; j < KSEL; j += 32) acc += s_e[j];
#pragma unroll
        for (int o = 16; o > 0; o >>= 1)
            acc += __shfl_xor_sync(0xFFFFFFFFu, acc, o);
        if (tid == 0) s_sum = acc;
    }
    __syncthreads();
    if (tid < KSEL) {
        int idx = (int)(~(unsigned)s_key[tid]);
        out[b * KSEL + tid]             = values[b * L_ + idx];   // values_sel
        out[B_ * KSEL + b * KSEL + tid] = e / s_sum;              // weights
    }
}

// ---------------------------------------------------------------------------
extern "C" void kernel_launch(void* const* d_in, const int* in_sizes, int n_in,
                              void* d_out, int out_size)
{
    const float* q      = (const float*)d_in[0];
    const float* keys   = (const float*)d_in[1];
    const float* values = (const float*)d_in[2];
    const float* g      = (const float*)d_in[3];
    float* out = (float*)d_out;

    (void)in_sizes; (void)n_in; (void)out_size;

    const int smemA = 2 * TILE * ROWW * 4;   // 69632 B
    cudaFuncSetAttribute(sim_kernel,
                         cudaFuncAttributeMaxDynamicSharedMemorySize, smemA);
    dim3 gridA(L_ / (TILE * NT), B_);
    sim_kernel<<<gridA, TILE, smemA>>>(q, keys, g);

    topk_kernel<<<B_, 256>>>(values, out);
}

// round 5
// speedup vs baseline: 1.7728x; 1.7728x over previous
#include <cuda_runtime.h>
#include <cuda_bf16.h>

#define B_    64
#define L_    16384
#define D_    64
#define KSEL  256
#define TILE  128
#define NT    4                      // tiles per CTA (double-buffered)
#define ROWW  68
#define NBINS 4096
#define CAP   2048

__device__ float g_sim[B_ * L_];
__device__ unsigned g_hist[B_ * NBINS];   // zero-init; kernel B re-zeroes

__device__ __forceinline__ unsigned f2u(float f) {
    unsigned b = __float_as_uint(f);
    return (b & 0x80000000u) ? ~b : (b | 0x80000000u);
}
__device__ __forceinline__ float u2f(unsigned u) {
    unsigned b = (u & 0x80000000u) ? (u & 0x7FFFFFFFu) : ~u;
    return __uint_as_float(b);
}

// ---------------------------------------------------------------------------
// Kernel A: sims + per-batch 12-bit histogram. 4 tiles/CTA, 2-stage pipeline.
// ---------------------------------------------------------------------------
__global__ void __launch_bounds__(TILE) sim_kernel(
    const float* __restrict__ q,
    const float* __restrict__ keys,
    const float* __restrict__ gp)
{
    extern __shared__ __align__(16) float tile[];   // [2][TILE*ROWW]
    __shared__ __align__(16) float4 qsm[D_ / 4];

    const int b   = blockIdx.y;
    const int t0  = blockIdx.x * (TILE * NT);
    const int tid = threadIdx.x;

    if (tid < D_ / 4)
        qsm[tid] = reinterpret_cast<const float4*>(q + b * D_)[tid];

    const float4* kbase = reinterpret_cast<const float4*>(
        keys + (size_t)b * L_ * D_ + (size_t)t0 * D_);

    auto issue = [&](int tt, int buf) {
        const float4* src = kbase + tt * (TILE * 16);
        float* dstbase = tile + buf * (TILE * ROWW);
#pragma unroll
        for (int j = 0; j < 16; j++) {
            int f = j * TILE + tid;
            int l = f >> 4;
            int c = f & 15;
            unsigned dst = (unsigned)__cvta_generic_to_shared(
                &dstbase[l * ROWW + c * 4]);
            asm volatile("cp.async.cg.shared.global [%0], [%1], 16;\n"
                         :: "r"(dst), "l"(src + f));
        }
        asm volatile("cp.async.commit_group;\n");
    };

    issue(0, 0);

    __syncthreads();   // qsm visible
    float qq = 0.f;
#pragma unroll
    for (int i = 0; i < D_ / 4; i++) {
        float4 t = qsm[i];
        qq += t.x * t.x + t.y * t.y + t.z * t.z + t.w * t.w;
    }
    const float rq = gp[0] * rsqrtf(qq);

#pragma unroll
    for (int t = 0; t < NT; t++) {
        if (t + 1 < NT) {
            issue(t + 1, (t + 1) & 1);
            asm volatile("cp.async.wait_group 1;\n");
        } else {
            asm volatile("cp.async.wait_group 0;\n");
        }
        __syncthreads();

        const float* tb = tile + (t & 1) * (TILE * ROWW);
        float dot = 0.f, kk = 0.f;
#pragma unroll
        for (int i = 0; i < 16; i++) {
            float4 kv = *reinterpret_cast<const float4*>(&tb[tid * ROWW + i * 4]);
            float4 qv = qsm[i];
            dot += qv.x * kv.x + qv.y * kv.y + qv.z * kv.z + qv.w * kv.w;
            kk  += kv.x * kv.x + kv.y * kv.y + kv.z * kv.z + kv.w * kv.w;
        }
        float sim = dot * rq * rsqrtf(kk);
        g_sim[b * L_ + t0 + t * TILE + tid] = sim;
        atomicAdd(&g_hist[b * NBINS + (f2u(sim) >> 20)], 1u);

        __syncthreads();
    }
}

// ---------------------------------------------------------------------------
// Kernel B: per-batch threshold (parallel 3-level suffix scan) + collect +
// O(n^2) rank + softmax + gather. One CTA per batch, 1024 threads.
// ---------------------------------------------------------------------------
__global__ void __launch_bounds__(1024) topk_kernel(
    const float* __restrict__ values,
    float* __restrict__ out)
{
    __shared__ __align__(16) unsigned long long cand[CAP];  // 16 KB
    __shared__ unsigned long long s_key[KSEL];              // 2 KB
    __shared__ float s_e[KSEL];
    __shared__ float s_sum;
    __shared__ int   s_n;
    __shared__ unsigned s_lo;
    __shared__ unsigned s_wtot[32], s_wabove[32];

    const int b    = blockIdx.x;
    const int tid  = threadIdx.x;
    const int lane = tid & 31;
    const int warp = tid >> 5;

    // --- 1. histogram: 4 bins/thread in registers; re-zero global copy ---
    uint4 h = reinterpret_cast<const uint4*>(g_hist + b * NBINS)[tid];
    reinterpret_cast<uint4*>(g_hist + b * NBINS)[tid] = make_uint4(0, 0, 0, 0);
    unsigned sum4 = h.x + h.y + h.z + h.w;

    // warp-level inclusive suffix (higher lanes = higher bins)
    unsigned suf = sum4;
#pragma unroll
    for (int o = 1; o < 32; o <<= 1) {
        unsigned t = __shfl_down_sync(0xFFFFFFFFu, suf, o);
        if (lane + o < 32) suf += t;
    }
    if (lane == 0) s_wtot[warp] = suf;
    if (tid == 0) s_n = 0;
    __syncthreads();

    // warp 0: suffix over the 32 warp totals
    if (warp == 0) {
        unsigned wt = s_wtot[lane];
        unsigned wsuf = wt;
#pragma unroll
        for (int o = 1; o < 32; o <<= 1) {
            unsigned t = __shfl_down_sync(0xFFFFFFFFu, wsuf, o);
            if (lane + o < 32) wsuf += t;
        }
        s_wabove[lane] = wsuf - wt;   // count in warps strictly above
    }
    __syncthreads();

    // exactly one thread's 4-bin group contains the 256th element
    unsigned above = s_wabove[warp] + (suf - sum4);
    if (above < KSEL && above + sum4 >= KSEL) {
        unsigned hh[4] = {h.x, h.y, h.z, h.w};
        unsigned acc = above;
        int bin = 4 * tid;
        for (int j = 3; j >= 0; j--) {
            if (acc + hh[j] >= KSEL) { bin = 4 * tid + j; break; }
            acc += hh[j];
        }
        s_lo = ((unsigned)bin) << 20;
    }
    __syncthreads();
    const unsigned lo = s_lo;

    // --- 2. collect candidates >= threshold (hoisted loads, MLP=4) ---
    const float4* simrow4 = reinterpret_cast<const float4*>(g_sim + b * L_);
    float4 sv[4];
#pragma unroll
    for (int r = 0; r < 4; r++)
        sv[r] = simrow4[r * 1024 + tid];

#pragma unroll
    for (int r = 0; r < 4; r++) {
        unsigned u4[4] = {f2u(sv[r].x), f2u(sv[r].y), f2u(sv[r].z), f2u(sv[r].w)};
#pragma unroll
        for (int c = 0; c < 4; c++) {
            bool take = (u4[c] >= lo);
            unsigned m = __ballot_sync(0xFFFFFFFFu, take);
            if (m) {
                int leader = __ffs(m) - 1;
                int basepos = 0;
                if (lane == leader)
                    basepos = atomicAdd(&s_n, __popc(m));
                basepos = __shfl_sync(0xFFFFFFFFu, basepos, leader);
                if (take) {
                    int p = basepos + __popc(m & ((1u << lane) - 1));
                    int i = (r * 1024 + tid) * 4 + c;
                    if (p < CAP)
                        cand[p] = ((unsigned long long)u4[c] << 32) |
                                  (unsigned)(~i);
                }
            }
        }
    }
    __syncthreads();

    // --- 3. exact rank (desc value, asc index): O(n^2), broadcast LDS ---
    int n = s_n; if (n > CAP) n = CAP;
    for (int i = tid; i < n; i += 1024) {
        unsigned long long me = cand[i];
        int r = 0;
        for (int j = 0; j < n; j++)
            r += (cand[j] > me);
        if (r < KSEL)
            s_key[r] = me;
    }
    __syncthreads();

    // --- 4. softmax over top-256 + gather + output ---
    float maxs = u2f((unsigned)(s_key[0] >> 32));
    float e = 0.f;
    if (tid < KSEL) {
        e = expf(u2f((unsigned)(s_key[tid] >> 32)) - maxs);
        s_e[tid] = e;
    }
    __syncthreads();
    if (tid < 32) {
        float acc = 0.f;
#pragma unroll
        for (int j = 0; j < KSEL / 32; j++) acc += s_e[tid + j * 32];
#pragma unroll
        for (int o = 16; o > 0; o >>= 1)
            acc += __shfl_xor_sync(0xFFFFFFFFu, acc, o);
        if (tid == 0) s_sum = acc;
    }
    __syncthreads();
    if (tid < KSEL) {
        int idx = (int)(~(unsigned)s_key[tid]);
        out[b * KSEL + tid]             = values[b * L_ + idx];   // values_sel
        out[B_ * KSEL + b * KSEL + tid] = e / s_sum;              // weights
    }
}

// ---------------------------------------------------------------------------
extern "C" void kernel_launch(void* const* d_in, const int* in_sizes, int n_in,
                              void* d_out, int out_size)
{
    const float* q      = (const float*)d_in[0];
    const float* keys   = (const float*)d_in[1];
    const float* values = (const float*)d_in[2];
    const float* g      = (const float*)d_in[3];
    float* out = (float*)d_out;

    (void)in_sizes; (void)n_in; (void)out_size;

    const int smemA = 2 * TILE * ROWW * 4;   // 69632 B
    cudaFuncSetAttribute(sim_kernel,
                         cudaFuncAttributeMaxDynamicSharedMemorySize, smemA);
    dim3 gridA(L_ / (TILE * NT), B_);
    sim_kernel<<<gridA, TILE, smemA>>>(q, keys, g);

    topk_kernel<<<B_, 1024>>>(values, out);
}